// round 10
// baseline (speedup 1.0000x reference)
#include <cuda_runtime.h>
#include <cuda_bf16.h>

#define NNODE 128
#define NM1   127             // edges per receiver
#define NRR   (NNODE * NM1)   // 16256 directed edges
#define BB    128
#define CC    16
#define RPC   2               // receivers per CTA
#define THREADS 256
#define F4_PER_R   (NM1 * 4)        // 508 float4s per receiver
#define F4_PER_CTA (RPC * F4_PER_R) // 1016
#define R_STRIDE   8192             // smem bytes per receiver region (8128+pad)

// SW128 swizzle: XOR bits [9:7] into [6:4]. Region bases are multiples of
// 8192 (row-aligned) so the swizzle composes with the region offset.
__device__ __forceinline__ unsigned swz(unsigned byte_off) {
    return byte_off ^ ((byte_off >> 3) & 0x70u);
}

// One CTA per (batch b, receiver pair rp). 256 threads.
//
// Phase 1: f = t + 256j over 1016 float4s -> every LDG.128 is a 128B-aligned
//          contiguous 512B warp transaction (base = rp*16256B = 127*128).
//          exp() accumulated DIRECTLY from load registers into two per-thread
//          float4 accs (receiver selected by edge index); raw x staged once
//          into swizzled smem for the phase-2 transpose.
// Reduce:  3-stage xor-shuffle (masks 4,8,16) per acc; 8-warp combine via
//          ~1KB smem; 32 threads compute one __frcp_rn per (receiver,channel).
// Phase 2: thread t = edge within the 254-edge pair; 4 conflict-free LDS.128,
//          scale, 16 STG.32 -> per channel the CTA writes one contiguous
//          1016B run (partial sectors halved vs R8).
__global__ __launch_bounds__(THREADS) void attention2_denom_kernel(
    const float* __restrict__ x, float* __restrict__ out)
{
    const int rp   = blockIdx.x;         // receiver pair [0,64)
    const int b    = blockIdx.y;
    const int t    = threadIdx.x;
    const int warp = t >> 5;
    const int lane = t & 31;

    __shared__ __align__(16) unsigned char v_s[RPC * R_STRIDE];  // 16KB staged x
    __shared__ float4 ws4[8][RPC][4];    // [warp][receiver][quad]
    __shared__ float4 rden4[RPC][4];     // reciprocals

    const float4* __restrict__ src = reinterpret_cast<const float4*>(
        x + ((size_t)b * NRR + (size_t)rp * (RPC * NM1)) * CC);

    // ---- Phase 1: aligned coalesced load; exp from registers; stage --------
    float4 acc0 = make_float4(0.f, 0.f, 0.f, 0.f);
    float4 acc1 = make_float4(0.f, 0.f, 0.f, 0.f);
    #pragma unroll
    for (int j = 0; j < 4; j++) {
        int f = t + THREADS * j;                       // [0, 1024)
        if (f < F4_PER_CTA) {                          // j=3 predicated (t<248)
            float4 g = __ldcs(src + f);
            int e  = f >> 2;                           // edge within pair [0,254)
            int rr = (e >= NM1);                       // receiver 0 or 1
            float4& a = rr ? acc1 : acc0;
            a.x += __expf(g.x);
            a.y += __expf(g.y);
            a.z += __expf(g.z);
            a.w += __expf(g.w);
            unsigned fl = (unsigned)(f - rr * F4_PER_R);
            *reinterpret_cast<float4*>(v_s + rr * R_STRIDE + swz(16u * fl)) = g;
        }
    }

    // Lanes sharing channel-quad q = t&3 differ in bits {2,3,4}: masks 4,8,16.
    #pragma unroll
    for (int m = 4; m <= 16; m <<= 1) {
        acc0.x += __shfl_xor_sync(0xffffffffu, acc0.x, m);
        acc0.y += __shfl_xor_sync(0xffffffffu, acc0.y, m);
        acc0.z += __shfl_xor_sync(0xffffffffu, acc0.z, m);
        acc0.w += __shfl_xor_sync(0xffffffffu, acc0.w, m);
        acc1.x += __shfl_xor_sync(0xffffffffu, acc1.x, m);
        acc1.y += __shfl_xor_sync(0xffffffffu, acc1.y, m);
        acc1.z += __shfl_xor_sync(0xffffffffu, acc1.z, m);
        acc1.w += __shfl_xor_sync(0xffffffffu, acc1.w, m);
    }
    if (lane < 4) {                       // lane == its quad q
        ws4[warp][0][lane] = acc0;
        ws4[warp][1][lane] = acc1;
    }
    __syncthreads();

    if (t < RPC * CC) {                   // 32 threads: one (receiver,channel)
        const int g = t >> 4;
        const int c = t & 15;
        float d = 0.f;
        #pragma unroll
        for (int w = 0; w < 8; w++)
            d += reinterpret_cast<const float*>(ws4[w][g])[c];
        reinterpret_cast<float*>(rden4[g])[c] = __frcp_rn(d);
    }
    __syncthreads();

    // ---- Phase 2: edge-owned readback + contiguous transposed stores --------
    if (t < RPC * NM1) {                  // edge within the 254-edge pair
        const int g = (t >= NM1);
        const int u = t - g * NM1;
        const unsigned char* base = v_s + g * R_STRIDE;

        float4 rd0 = rden4[g][0], rd1 = rden4[g][1];
        float4 rd2 = rden4[g][2], rd3 = rden4[g][3];
        float4 v0 = *reinterpret_cast<const float4*>(base + swz(16u * (4u * u + 0)));
        float4 v1 = *reinterpret_cast<const float4*>(base + swz(16u * (4u * u + 1)));
        float4 v2 = *reinterpret_cast<const float4*>(base + swz(16u * (4u * u + 2)));
        float4 v3 = *reinterpret_cast<const float4*>(base + swz(16u * (4u * u + 3)));

        float* o = out + (size_t)b * CC * NRR + (size_t)rp * (RPC * NM1) + (size_t)t;
        o[ 0 * NRR] = v0.x * rd0.x;  o[ 1 * NRR] = v0.y * rd0.y;
        o[ 2 * NRR] = v0.z * rd0.z;  o[ 3 * NRR] = v0.w * rd0.w;
        o[ 4 * NRR] = v1.x * rd1.x;  o[ 5 * NRR] = v1.y * rd1.y;
        o[ 6 * NRR] = v1.z * rd1.z;  o[ 7 * NRR] = v1.w * rd1.w;
        o[ 8 * NRR] = v2.x * rd2.x;  o[ 9 * NRR] = v2.y * rd2.y;
        o[10 * NRR] = v2.z * rd2.z;  o[11 * NRR] = v2.w * rd2.w;
        o[12 * NRR] = v3.x * rd3.x;  o[13 * NRR] = v3.y * rd3.y;
        o[14 * NRR] = v3.z * rd3.z;  o[15 * NRR] = v3.w * rd3.w;
    }
}

extern "C" void kernel_launch(void* const* d_in, const int* in_sizes, int n_in,
                              void* d_out, int out_size)
{
    // d_in[0]: x  float32 [B, NR, C]
    // d_in[1]: receivers int32 [NR] — structurally i/(N-1), unused
    const float* x   = (const float*)d_in[0];
    float*       out = (float*)d_out;   // float32 [B, C, NR]

    dim3 grid(NNODE / RPC, BB);   // (receiver-pair, batch)
    attention2_denom_kernel<<<grid, THREADS>>>(x, out);
}

// round 11
// speedup vs baseline: 1.0058x; 1.0058x over previous
#include <cuda_runtime.h>
#include <cuda_bf16.h>

#define NNODE 128
#define NM1   127             // edges per receiver
#define NRR   (NNODE * NM1)   // 16256 directed edges
#define BB    128
#define CC    16
#define RPC   2               // receivers per CTA
#define THREADS 256
#define F4_PER_R   (NM1 * 4)        // 508 float4s per receiver
#define F4_PER_CTA (RPC * F4_PER_R) // 1016
#define R_STRIDE   8192             // smem bytes per receiver region (8128+pad)

// SW128 swizzle: XOR bits [9:7] into [6:4]. Region bases are multiples of
// 8192 (row-aligned) so the swizzle composes with the region offset.
__device__ __forceinline__ unsigned swz(unsigned byte_off) {
    return byte_off ^ ((byte_off >> 3) & 0x70u);
}

// One CTA per (batch b, receiver pair rp). 256 threads.
//
// Phase 1: f = t + 256j over 1016 float4s -> every LDG.128 is a 128B-aligned
//          contiguous 512B warp transaction (base = rp*16256B = 127*128).
//          exp() accumulated DIRECTLY from load registers into two per-thread
//          float4 accs (receiver selected by edge index); raw x staged once
//          into swizzled smem for the phase-2 transpose.
// Reduce:  3-stage xor-shuffle (masks 4,8,16) per acc; 8-warp combine via
//          ~1KB smem; 32 threads compute one __frcp_rn per (receiver,channel).
// Phase 2: thread t = edge within the 254-edge pair; 4 conflict-free LDS.128,
//          scale, 16 STG.32 -> per channel the CTA writes one contiguous
//          1016B run (partial sectors halved vs R8).
__global__ __launch_bounds__(THREADS) void attention2_denom_kernel(
    const float* __restrict__ x, float* __restrict__ out)
{
    const int rp   = blockIdx.x;         // receiver pair [0,64)
    const int b    = blockIdx.y;
    const int t    = threadIdx.x;
    const int warp = t >> 5;
    const int lane = t & 31;

    __shared__ __align__(16) unsigned char v_s[RPC * R_STRIDE];  // 16KB staged x
    __shared__ float4 ws4[8][RPC][4];    // [warp][receiver][quad]
    __shared__ float4 rden4[RPC][4];     // reciprocals

    const float4* __restrict__ src = reinterpret_cast<const float4*>(
        x + ((size_t)b * NRR + (size_t)rp * (RPC * NM1)) * CC);

    // ---- Phase 1: aligned coalesced load; exp from registers; stage --------
    float4 acc0 = make_float4(0.f, 0.f, 0.f, 0.f);
    float4 acc1 = make_float4(0.f, 0.f, 0.f, 0.f);
    #pragma unroll
    for (int j = 0; j < 4; j++) {
        int f = t + THREADS * j;                       // [0, 1024)
        if (f < F4_PER_CTA) {                          // j=3 predicated (t<248)
            float4 g = __ldcs(src + f);
            int e  = f >> 2;                           // edge within pair [0,254)
            int rr = (e >= NM1);                       // receiver 0 or 1
            float4& a = rr ? acc1 : acc0;
            a.x += __expf(g.x);
            a.y += __expf(g.y);
            a.z += __expf(g.z);
            a.w += __expf(g.w);
            unsigned fl = (unsigned)(f - rr * F4_PER_R);
            *reinterpret_cast<float4*>(v_s + rr * R_STRIDE + swz(16u * fl)) = g;
        }
    }

    // Lanes sharing channel-quad q = t&3 differ in bits {2,3,4}: masks 4,8,16.
    #pragma unroll
    for (int m = 4; m <= 16; m <<= 1) {
        acc0.x += __shfl_xor_sync(0xffffffffu, acc0.x, m);
        acc0.y += __shfl_xor_sync(0xffffffffu, acc0.y, m);
        acc0.z += __shfl_xor_sync(0xffffffffu, acc0.z, m);
        acc0.w += __shfl_xor_sync(0xffffffffu, acc0.w, m);
        acc1.x += __shfl_xor_sync(0xffffffffu, acc1.x, m);
        acc1.y += __shfl_xor_sync(0xffffffffu, acc1.y, m);
        acc1.z += __shfl_xor_sync(0xffffffffu, acc1.z, m);
        acc1.w += __shfl_xor_sync(0xffffffffu, acc1.w, m);
    }
    if (lane < 4) {                       // lane == its quad q
        ws4[warp][0][lane] = acc0;
        ws4[warp][1][lane] = acc1;
    }
    __syncthreads();

    if (t < RPC * CC) {                   // 32 threads: one (receiver,channel)
        const int g = t >> 4;
        const int c = t & 15;
        float d = 0.f;
        #pragma unroll
        for (int w = 0; w < 8; w++)
            d += reinterpret_cast<const float*>(ws4[w][g])[c];
        reinterpret_cast<float*>(rden4[g])[c] = __frcp_rn(d);
    }
    __syncthreads();

    // ---- Phase 2: edge-owned readback + contiguous transposed stores --------
    if (t < RPC * NM1) {                  // edge within the 254-edge pair
        const int g = (t >= NM1);
        const int u = t - g * NM1;
        const unsigned char* base = v_s + g * R_STRIDE;

        float4 rd0 = rden4[g][0], rd1 = rden4[g][1];
        float4 rd2 = rden4[g][2], rd3 = rden4[g][3];
        float4 v0 = *reinterpret_cast<const float4*>(base + swz(16u * (4u * u + 0)));
        float4 v1 = *reinterpret_cast<const float4*>(base + swz(16u * (4u * u + 1)));
        float4 v2 = *reinterpret_cast<const float4*>(base + swz(16u * (4u * u + 2)));
        float4 v3 = *reinterpret_cast<const float4*>(base + swz(16u * (4u * u + 3)));

        float* o = out + (size_t)b * CC * NRR + (size_t)rp * (RPC * NM1) + (size_t)t;
        o[ 0 * NRR] = v0.x * rd0.x;  o[ 1 * NRR] = v0.y * rd0.y;
        o[ 2 * NRR] = v0.z * rd0.z;  o[ 3 * NRR] = v0.w * rd0.w;
        o[ 4 * NRR] = v1.x * rd1.x;  o[ 5 * NRR] = v1.y * rd1.y;
        o[ 6 * NRR] = v1.z * rd1.z;  o[ 7 * NRR] = v1.w * rd1.w;
        o[ 8 * NRR] = v2.x * rd2.x;  o[ 9 * NRR] = v2.y * rd2.y;
        o[10 * NRR] = v2.z * rd2.z;  o[11 * NRR] = v2.w * rd2.w;
        o[12 * NRR] = v3.x * rd3.x;  o[13 * NRR] = v3.y * rd3.y;
        o[14 * NRR] = v3.z * rd3.z;  o[15 * NRR] = v3.w * rd3.w;
    }
}

extern "C" void kernel_launch(void* const* d_in, const int* in_sizes, int n_in,
                              void* d_out, int out_size)
{
    // d_in[0]: x  float32 [B, NR, C]
    // d_in[1]: receivers int32 [NR] — structurally i/(N-1), unused
    const float* x   = (const float*)d_in[0];
    float*       out = (float*)d_out;   // float32 [B, C, NR]

    dim3 grid(NNODE / RPC, BB);   // (receiver-pair, batch)
    attention2_denom_kernel<<<grid, THREADS>>>(x, out);
}